// round 13
// baseline (speedup 1.0000x reference)
#include <cuda_runtime.h>

// Problem constants
#define K_COLORS 512
#define NGRP     (K_COLORS / 4)       // 128 groups of 4 colors
#define HW       65536                // 256*256
#define B        8
#define PPT      4                    // pixels (batch images) per thread
#define NTHREADS 128
#define NBLOCKS  1024                 // 131072 threads = HW * (B/PPT)
#define NPIX     (HW * B)             // 524288
#define NOUT     (NPIX * 3)           // 1572864

// One group = 4 consecutive colors, coefficients pre-paired for f32x2 math:
// a0 = {(-2t0_k,-2t0_k+1),(-2t0_k+2,-2t0_k+3)}, likewise a1/a2/nn.
struct Grp { ulonglong2 a0, a1, a2, nn; };

__constant__ Grp    cG[NGRP];         // full palette in const bank
__device__   Grp    gG[NGRP];         // staging, written by prep_kernel
__device__   float4 gC4[K_COLORS];    // AoS (-2t0,-2t1,-2t2,n) for the rescan

__device__ float        g_partials[NBLOCKS];
__device__ unsigned int g_count = 0;

// ---- packed f32x2 helpers ----
__device__ __forceinline__ unsigned long long fma2(unsigned long long a,
                                                   unsigned long long b,
                                                   unsigned long long c) {
    unsigned long long d;
    asm("fma.rn.f32x2 %0, %1, %2, %3;" : "=l"(d) : "l"(a), "l"(b), "l"(c));
    return d;
}
__device__ __forceinline__ unsigned long long bc2(float x) {
    unsigned int u = __float_as_uint(x);
    return ((unsigned long long)u << 32) | u;
}
__device__ __forceinline__ float lo_f(unsigned long long v) {
    return __uint_as_float((unsigned int)v);
}
__device__ __forceinline__ float hi_f(unsigned long long v) {
    return __uint_as_float((unsigned int)(v >> 32));
}

__global__ void __launch_bounds__(K_COLORS) prep_kernel(
    const float* __restrict__ table)
{
    const int k = threadIdx.x;
    float t0 = table[3 * k + 0];
    float t1 = table[3 * k + 1];
    float t2 = table[3 * k + 2];
    float n  = __fadd_rn(__fadd_rn(__fmul_rn(t0, t0), __fmul_rn(t1, t1)),
                         __fmul_rn(t2, t2));
    float a0 = -2.0f * t0, a1 = -2.0f * t1, a2 = -2.0f * t2;
    const int g4 = k >> 2, lane = k & 3;
    float* base = (float*)&gG[g4];
    base[0 * 4 + lane] = a0;
    base[1 * 4 + lane] = a1;
    base[2 * 4 + lane] = a2;
    base[3 * 4 + lane] = n;
    gC4[k] = make_float4(a0, a1, a2, n);
}

// Fused VQ + straight-through output + loss.
//
// ROUND-13 CHANGES vs round 12 (53.7us):
//  (a) PORT INTERLEAVE: round 12 split palette reads const-then-smem in two
//      SEQUENTIAL phases, so the two ports' serialized costs added instead
//      of overlapping. Here every macro-step of 4 groups reads group 4m via
//      the constant port (LDC) and groups 4m+1..3 via shared memory (LDS),
//      so both ports stream concurrently. Both copies hold identical bits
//      and the scan stays in ascending g4 order -> tie semantics unchanged.
//  (b) REGISTER HEADROOM: per-warp issue rate measured ~1 instr/14 cyc in
//      rounds 9/12 — with <=68 regs ptxas serialized the 4 pixel chains and
//      couldn't pipeline the 64B/group coefficient loads. __launch_bounds__
//      (128, 4) allows ~128 regs so chains interleave and loads run ahead;
//      occupancy drops to 16 warps/SM, traded for >=2x per-warp IPC.
//
// Exactness: strict '<' commit in ascending group order (earliest group on
// ties); final 4-color rescan recomputes the bit-identical scalar FMA chain
// (f32x2 halves are IEEE-identical to fma.rn.f32); first '==' match is the
// argmin (jnp.argmin first-index semantics). Bit-validated rounds 4/6-12.
__global__ void __launch_bounds__(NTHREADS, 4) vq_kernel(
    const float* __restrict__ z,
    float* __restrict__ out,
    int out_size)
{
    __shared__ Grp   sG[NGRP];         // full palette copy (8 KB)
    __shared__ float sred[NTHREADS];
    __shared__ int   s_last;

    const int tid  = threadIdx.x;

    // Cooperative copy of the palette into smem (512 x 16B).
    {
        const ulonglong2* src = (const ulonglong2*)gG;
        ulonglong2*       dst = (ulonglong2*)sG;
#pragma unroll
        for (int i = tid; i < NGRP * 4; i += NTHREADS) dst[i] = src[i];
    }

    const int g    = blockIdx.x * NTHREADS + tid;   // 0..131071
    const int hw   = g & (HW - 1);
    const int bat0 = (g >> 16) * PPT;               // first batch image

    // Pixel components broadcast into both packed halves (loop-invariant).
    unsigned long long Xb[PPT], Yb[PPT], Zb[PPT];
#pragma unroll
    for (int p = 0; p < PPT; ++p) {
        const int base = (bat0 + p) * 3 * HW + hw;
        Xb[p] = bc2(z[base]);
        Yb[p] = bc2(z[base + HW]);
        Zb[p] = bc2(z[base + 2 * HW]);
    }

    float gbest[PPT];
    int   ggrp[PPT];
#pragma unroll
    for (int p = 0; p < PPT; ++p) { gbest[p] = 3.402823466e38f; ggrp[p] = 0; }

    __syncthreads();   // smem palette ready

    // One 4-color group: 8 independent packed FMA chains first (4 pixels),
    // then the min trees — maximizes schedulable ILP per warp.
    auto process = [&](const Grp gr, const int g4) {
        unsigned long long d01[PPT], d23[PPT];
#pragma unroll
        for (int p = 0; p < PPT; ++p) {
            // d = x*(-2t0) + (y*(-2t1) + (z*(-2t2) + n)) — same chain
            // order/rounding as the reference scalar fmaf chain.
            d01[p] = fma2(Xb[p], gr.a0.x,
                          fma2(Yb[p], gr.a1.x, fma2(Zb[p], gr.a2.x, gr.nn.x)));
            d23[p] = fma2(Xb[p], gr.a0.y,
                          fma2(Yb[p], gr.a1.y, fma2(Zb[p], gr.a2.y, gr.nn.y)));
        }
#pragma unroll
        for (int p = 0; p < PPT; ++p) {
            float m = fminf(fminf(lo_f(d01[p]), hi_f(d01[p])),
                            fminf(lo_f(d23[p]), hi_f(d23[p])));
            bool lt  = m < gbest[p];               // earliest group on ties
            gbest[p] = fminf(gbest[p], m);
            ggrp[p]  = lt ? g4 : ggrp[p];
        }
    };

    // Interleaved ports: group 4m from const bank, 4m+1..3 from smem.
#pragma unroll 2
    for (int mq = 0; mq < NGRP / 4; ++mq) {
        const int gb = mq << 2;
        process(cG[gb + 0], gb + 0);               // LDC  (const port)
        process(sG[gb + 1], gb + 1);               // LDS  (shared port)
        process(sG[gb + 2], gb + 2);
        process(sG[gb + 3], gb + 3);
    }

    // Exact index recovery (first '==' match inside the winning 4-color
    // group), fused with the STE epilogue + loss accumulation.
    float lsum = 0.0f;
#pragma unroll
    for (int p = 0; p < PPT; ++p) {
        const int   kb = ggrp[p] << 2;
        const float px = lo_f(Xb[p]);
        const float py = lo_f(Yb[p]);
        const float pz = lo_f(Zb[p]);
        int found = 1023;
#pragma unroll
        for (int i = 0; i < 4; ++i) {
            const float4 cc = __ldg(&gC4[kb + i]);
            float d = fmaf(px, cc.x, fmaf(py, cc.y, fmaf(pz, cc.z, cc.w)));
            int kc = (d == gbest[p]) ? (kb + i) : 1023;
            found  = min(found, kc);
        }
        const float4 cc = __ldg(&gC4[found]);
        float q0 = -0.5f * cc.x;                 // exact recovery of t from -2t
        float q1 = -0.5f * cc.y;
        float q2 = -0.5f * cc.z;
        float d0 = __fsub_rn(q0, px);
        float d1 = __fsub_rn(q1, py);
        float d2 = __fsub_rn(q2, pz);
        const int base = (bat0 + p) * 3 * HW + hw;
        out[base]          = __fadd_rn(px, d0);  // zl + (z_q - zl)
        out[base + HW]     = __fadd_rn(py, d1);
        out[base + 2 * HW] = __fadd_rn(pz, d2);
        lsum = fmaf(d0, d0, lsum);
        lsum = fmaf(d1, d1, lsum);
        lsum = fmaf(d2, d2, lsum);
    }

    // Deterministic block reduction.
    sred[tid] = lsum;
    __syncthreads();
#pragma unroll
    for (int s = NTHREADS / 2; s > 0; s >>= 1) {
        if (tid < s) sred[tid] += sred[tid + s];
        __syncthreads();
    }

    // Last-block-done final reduction (single fused kernel).
    if (tid == 0) {
        g_partials[blockIdx.x] = sred[0];
        __threadfence();
        unsigned int prev = atomicAdd(&g_count, 1u);
        s_last = (prev == NBLOCKS - 1) ? 1 : 0;
    }
    __syncthreads();

    if (s_last) {
        __threadfence();
        volatile float* vp = g_partials;
        float acc = 0.0f;
        for (int i = tid; i < NBLOCKS; i += NTHREADS) acc += vp[i];
        sred[tid] = acc;
        __syncthreads();
#pragma unroll
        for (int s = NTHREADS / 2; s > 0; s >>= 1) {
            if (tid < s) sred[tid] += sred[tid + s];
            __syncthreads();
        }
        if (tid == 0) {
            float m    = sred[0] / (float)NOUT;
            float loss = __fadd_rn(10.0f * m, m);
            for (int i = NOUT; i < out_size; ++i) out[i] = loss;
            g_count = 0;   // reset for the next graph replay
        }
    }
}

extern "C" void kernel_launch(void* const* d_in, const int* in_sizes, int n_in,
                              void* d_out, int out_size)
{
    const float* z     = (const float*)d_in[0];
    const float* table = (const float*)d_in[1];
    float* out         = (float*)d_out;

    prep_kernel<<<1, K_COLORS>>>(table);

    // Stage -> constant bank, device-to-device async (graph-capturable).
    void* gG_addr = nullptr;
    cudaGetSymbolAddress(&gG_addr, gG);
    cudaMemcpyToSymbolAsync(cG, gG_addr, sizeof(gG), 0,
                            cudaMemcpyDeviceToDevice, 0);

    vq_kernel<<<NBLOCKS, NTHREADS>>>(z, out, out_size);
}

// round 14
// speedup vs baseline: 1.0387x; 1.0387x over previous
#include <cuda_runtime.h>

// Problem constants
#define K_COLORS 512
#define NGRP     (K_COLORS / 4)       // 128 groups of 4 colors
#define HW       65536                // 256*256
#define B        8
#define PPT      4                    // pixels (batch images) per thread
#define NTHREADS 128
#define NBLOCKS  1024                 // 131072 threads = HW * (B/PPT)
#define NPIX     (HW * B)             // 524288
#define NOUT     (NPIX * 3)           // 1572864

// One group = 4 consecutive colors, coefficients pre-paired for f32x2 math:
// a0 = {(-2t0_k,-2t0_k+1),(-2t0_k+2,-2t0_k+3)}, likewise a1/a2/nn.
struct Grp { ulonglong2 a0, a1, a2, nn; };

__constant__ Grp    cG[NGRP];         // full palette in const bank
__device__   Grp    gG[NGRP];         // staging, written by prep_kernel
__device__   float4 gC4[K_COLORS];    // AoS (-2t0,-2t1,-2t2,n) for the rescan

__device__ float        g_partials[NBLOCKS];
__device__ unsigned int g_count = 0;

__device__ __forceinline__ unsigned long long bc2(float x) {
    unsigned int u = __float_as_uint(x);
    return ((unsigned long long)u << 32) | u;
}
__device__ __forceinline__ float lo_f(unsigned long long v) {
    return __uint_as_float((unsigned int)v);
}

// ONE fused asm block per (group, pixel): 6x fma.rn.f32x2 + mov.b64 splits +
// 3x min.f32. Rounds 9-13 used one asm statement PER fma2 with 64-bit "l"
// operands — nvcc's per-statement operand marshalling generated MOV pairs
// around every fma2 (measured: ~2x more issues than source ops), which is
// why four different configs all pinned at ~51us with no pipe saturated.
// Binding all operands into a single block removes the marshalling.
//
// Chain order matches the reference scalar fmaf chain exactly:
//   d = fma(x, a0, fma(y, a1, fma(z, a2, n)))  per color (per packed half).
// min.f32 == fminf semantics (IEEE minNum); min is exact, tree unchanged.
__device__ __forceinline__ float group_min4(
    unsigned long long X, unsigned long long Y, unsigned long long Z,
    const Grp& gr)
{
    float m;
    asm("{\n\t"
        ".reg .b64 p, q;\n\t"
        ".reg .f32 a, b, c, d, u, v;\n\t"
        "fma.rn.f32x2 p, %3, %6, %7;\n\t"     // Z*a2.x + nn.x
        "fma.rn.f32x2 p, %2, %5, p;\n\t"      // Y*a1.x + p
        "fma.rn.f32x2 p, %1, %4, p;\n\t"      // X*a0.x + p  -> colors k,k+1
        "fma.rn.f32x2 q, %3, %10, %11;\n\t"   // Z*a2.y + nn.y
        "fma.rn.f32x2 q, %2, %9, q;\n\t"      // Y*a1.y + q
        "fma.rn.f32x2 q, %1, %8, q;\n\t"      // X*a0.y + q  -> colors k+2,k+3
        "mov.b64 {a, b}, p;\n\t"
        "mov.b64 {c, d}, q;\n\t"
        "min.f32 u, a, b;\n\t"
        "min.f32 v, c, d;\n\t"
        "min.f32 %0, u, v;\n\t"
        "}"
        : "=f"(m)
        : "l"(X), "l"(Y), "l"(Z),
          "l"(gr.a0.x), "l"(gr.a1.x), "l"(gr.a2.x), "l"(gr.nn.x),
          "l"(gr.a0.y), "l"(gr.a1.y), "l"(gr.a2.y), "l"(gr.nn.y));
    return m;
}

__global__ void __launch_bounds__(K_COLORS) prep_kernel(
    const float* __restrict__ table)
{
    const int k = threadIdx.x;
    float t0 = table[3 * k + 0];
    float t1 = table[3 * k + 1];
    float t2 = table[3 * k + 2];
    float n  = __fadd_rn(__fadd_rn(__fmul_rn(t0, t0), __fmul_rn(t1, t1)),
                         __fmul_rn(t2, t2));
    float a0 = -2.0f * t0, a1 = -2.0f * t1, a2 = -2.0f * t2;
    const int g4 = k >> 2, lane = k & 3;
    float* base = (float*)&gG[g4];
    base[0 * 4 + lane] = a0;
    base[1 * 4 + lane] = a1;
    base[2 * 4 + lane] = a2;
    base[3 * 4 + lane] = n;
    gC4[k] = make_float4(a0, a1, a2, n);
}

// Fused VQ + straight-through output + loss.
// Structure identical to round 13 (port-interleaved palette: group 4m from
// the const bank, 4m+1..3 from smem; ascending scan order) with the fused
// asm block above replacing the per-fma2 statements.
//
// Exactness: strict '<' commit in ascending group order (earliest group on
// ties); final 4-color rescan recomputes the bit-identical scalar FMA chain
// (f32x2 halves are IEEE-identical to fma.rn.f32); first '==' match is the
// argmin (jnp.argmin first-index semantics). Bit-validated rounds 4/6-13.
__global__ void __launch_bounds__(NTHREADS) vq_kernel(
    const float* __restrict__ z,
    float* __restrict__ out,
    int out_size)
{
    __shared__ Grp   sG[NGRP];         // full palette copy (8 KB)
    __shared__ float sred[NTHREADS];
    __shared__ int   s_last;

    const int tid  = threadIdx.x;

    // Cooperative copy of the palette into smem (512 x 16B).
    {
        const ulonglong2* src = (const ulonglong2*)gG;
        ulonglong2*       dst = (ulonglong2*)sG;
#pragma unroll
        for (int i = tid; i < NGRP * 4; i += NTHREADS) dst[i] = src[i];
    }

    const int g    = blockIdx.x * NTHREADS + tid;   // 0..131071
    const int hw   = g & (HW - 1);
    const int bat0 = (g >> 16) * PPT;               // first batch image

    // Pixel components broadcast into both packed halves (loop-invariant).
    unsigned long long Xb[PPT], Yb[PPT], Zb[PPT];
    float px[PPT], py[PPT], pz[PPT];
#pragma unroll
    for (int p = 0; p < PPT; ++p) {
        const int base = (bat0 + p) * 3 * HW + hw;
        px[p] = z[base];
        py[p] = z[base + HW];
        pz[p] = z[base + 2 * HW];
        Xb[p] = bc2(px[p]);
        Yb[p] = bc2(py[p]);
        Zb[p] = bc2(pz[p]);
    }

    float gbest[PPT];
    int   ggrp[PPT];
#pragma unroll
    for (int p = 0; p < PPT; ++p) { gbest[p] = 3.402823466e38f; ggrp[p] = 0; }

    __syncthreads();   // smem palette ready

    auto process = [&](const Grp gr, const int g4) {
        float m[PPT];
#pragma unroll
        for (int p = 0; p < PPT; ++p)
            m[p] = group_min4(Xb[p], Yb[p], Zb[p], gr);
#pragma unroll
        for (int p = 0; p < PPT; ++p) {
            bool lt  = m[p] < gbest[p];            // earliest group on ties
            gbest[p] = fminf(gbest[p], m[p]);
            ggrp[p]  = lt ? g4 : ggrp[p];
        }
    };

    // Interleaved ports: group 4m from const bank, 4m+1..3 from smem.
#pragma unroll 2
    for (int mq = 0; mq < NGRP / 4; ++mq) {
        const int gb = mq << 2;
        process(cG[gb + 0], gb + 0);               // LDC  (const port)
        process(sG[gb + 1], gb + 1);               // LDS  (shared port)
        process(sG[gb + 2], gb + 2);
        process(sG[gb + 3], gb + 3);
    }

    // Exact index recovery (first '==' match inside the winning 4-color
    // group), fused with the STE epilogue + loss accumulation.
    float lsum = 0.0f;
#pragma unroll
    for (int p = 0; p < PPT; ++p) {
        const int kb = ggrp[p] << 2;
        int found = 1023;
#pragma unroll
        for (int i = 0; i < 4; ++i) {
            const float4 cc = __ldg(&gC4[kb + i]);
            float d = fmaf(px[p], cc.x,
                           fmaf(py[p], cc.y, fmaf(pz[p], cc.z, cc.w)));
            int kc = (d == gbest[p]) ? (kb + i) : 1023;
            found  = min(found, kc);
        }
        const float4 cc = __ldg(&gC4[found]);
        float q0 = -0.5f * cc.x;                 // exact recovery of t from -2t
        float q1 = -0.5f * cc.y;
        float q2 = -0.5f * cc.z;
        float d0 = __fsub_rn(q0, px[p]);
        float d1 = __fsub_rn(q1, py[p]);
        float d2 = __fsub_rn(q2, pz[p]);
        const int base = (bat0 + p) * 3 * HW + hw;
        out[base]          = __fadd_rn(px[p], d0);  // zl + (z_q - zl)
        out[base + HW]     = __fadd_rn(py[p], d1);
        out[base + 2 * HW] = __fadd_rn(pz[p], d2);
        lsum = fmaf(d0, d0, lsum);
        lsum = fmaf(d1, d1, lsum);
        lsum = fmaf(d2, d2, lsum);
    }

    // Deterministic block reduction.
    sred[tid] = lsum;
    __syncthreads();
#pragma unroll
    for (int s = NTHREADS / 2; s > 0; s >>= 1) {
        if (tid < s) sred[tid] += sred[tid + s];
        __syncthreads();
    }

    // Last-block-done final reduction (single fused kernel).
    if (tid == 0) {
        g_partials[blockIdx.x] = sred[0];
        __threadfence();
        unsigned int prev = atomicAdd(&g_count, 1u);
        s_last = (prev == NBLOCKS - 1) ? 1 : 0;
    }
    __syncthreads();

    if (s_last) {
        __threadfence();
        volatile float* vp = g_partials;
        float acc = 0.0f;
        for (int i = tid; i < NBLOCKS; i += NTHREADS) acc += vp[i];
        sred[tid] = acc;
        __syncthreads();
#pragma unroll
        for (int s = NTHREADS / 2; s > 0; s >>= 1) {
            if (tid < s) sred[tid] += sred[tid + s];
            __syncthreads();
        }
        if (tid == 0) {
            float m    = sred[0] / (float)NOUT;
            float loss = __fadd_rn(10.0f * m, m);
            for (int i = NOUT; i < out_size; ++i) out[i] = loss;
            g_count = 0;   // reset for the next graph replay
        }
    }
}

extern "C" void kernel_launch(void* const* d_in, const int* in_sizes, int n_in,
                              void* d_out, int out_size)
{
    const float* z     = (const float*)d_in[0];
    const float* table = (const float*)d_in[1];
    float* out         = (float*)d_out;

    prep_kernel<<<1, K_COLORS>>>(table);

    // Stage -> constant bank, device-to-device async (graph-capturable).
    void* gG_addr = nullptr;
    cudaGetSymbolAddress(&gG_addr, gG);
    cudaMemcpyToSymbolAsync(cG, gG_addr, sizeof(gG), 0,
                            cudaMemcpyDeviceToDevice, 0);

    vq_kernel<<<NBLOCKS, NTHREADS>>>(z, out, out_size);
}